// round 1
// baseline (speedup 1.0000x reference)
#include <cuda_runtime.h>
#include <math.h>

// Linear_bin: binarized 5-layer MLP, B=32768, 64->2048->1024->512->64->1.
// Hidden activations are exactly {0,1} bits; weights are sign() = {-1,0,+1}.
// L1: fp32 FMA GEMM -> bitpack.  L2-L4: exact bitwise popcount GEMMs.
// L5 + sigmoid fused into the L4 kernel.

#define BATCH 32768
#define EPSBN 1e-5f

// ---------------- scratch (static device globals; no allocation) ----------------
__device__ __align__(16) float    d_s1k[64 * 2048];   // sign(w1), layout [(k>>2)*2048+j]*4+(k&3)
__device__ __align__(16) unsigned d_p2v[64 * 1024];   // w2>0 masks, [(w>>2)*1024+j]*4+(w&3)
__device__ __align__(16) unsigned d_z2 [64 * 1024];   // w2==0 masks, [w*1024+j]
__device__ int d_zf2[1024];
__device__ __align__(16) unsigned d_p3v[32 * 512];
__device__ __align__(16) unsigned d_z3 [32 * 512];
__device__ int d_zf3[512];
__device__ unsigned d_p4[64 * 16];
__device__ unsigned d_n4[64 * 16];
__device__ __align__(16) unsigned d_h1[BATCH * 64];   // layer-1 output bits
__device__ __align__(16) unsigned d_h2[BATCH * 32];
__device__ __align__(16) unsigned d_h3[BATCH * 16];

// ---------------- weight preprocessing (re-run every launch; deterministic) -----
__global__ void pack_s1(const float* __restrict__ w1) {
    int idx = blockIdx.x * 256 + threadIdx.x;          // 131072 threads
    int j = idx & 2047, k = idx >> 11;
    float v = w1[j * 64 + k];
    float s = (v > 0.f) ? 1.f : ((v < 0.f) ? -1.f : 0.f);
    d_s1k[((k >> 2) * 2048 + j) * 4 + (k & 3)] = s;
}

__global__ void pack_w(const float* __restrict__ w2, const float* __restrict__ w3,
                       const float* __restrict__ w4) {
    int idx = blockIdx.x * 256 + threadIdx.x;          // 82944 threads exactly
    if (idx < 65536) {                                 // layer 2: 1024 x 64 words
        int j = idx >> 6, w = idx & 63;
        unsigned p = 0, z = 0;
        #pragma unroll
        for (int i = 0; i < 32; i++) {
            float v = w2[j * 2048 + w * 32 + i];
            if (v > 0.f) p |= (1u << i);
            if (v == 0.f) z |= (1u << i);
        }
        d_p2v[((w >> 2) * 1024 + j) * 4 + (w & 3)] = p;
        d_z2[w * 1024 + j] = z;
    } else if (idx < 81920) {                          // layer 3: 512 x 32 words
        int t = idx - 65536; int j = t >> 5, w = t & 31;
        unsigned p = 0, z = 0;
        #pragma unroll
        for (int i = 0; i < 32; i++) {
            float v = w3[j * 1024 + w * 32 + i];
            if (v > 0.f) p |= (1u << i);
            if (v == 0.f) z |= (1u << i);
        }
        d_p3v[((w >> 2) * 512 + j) * 4 + (w & 3)] = p;
        d_z3[w * 512 + j] = z;
    } else {                                           // layer 4: 64 x 16 words
        int t = idx - 81920; int j = t >> 4, w = t & 15;
        unsigned p = 0, n = 0;
        #pragma unroll
        for (int i = 0; i < 32; i++) {
            float v = w4[j * 512 + w * 32 + i];
            if (v > 0.f) p |= (1u << i);
            if (v < 0.f) n |= (1u << i);
        }
        d_p4[j * 16 + w] = p;
        d_n4[j * 16 + w] = n;
    }
}

__global__ void zflags_kernel() {
    int idx = blockIdx.x * 256 + threadIdx.x;          // 1536 threads
    if (idx < 1024) {
        unsigned o = 0;
        for (int k = 0; k < 64; k++) o |= d_z2[k * 1024 + idx];
        d_zf2[idx] = (o != 0);
    } else if (idx < 1536) {
        int j = idx - 1024;
        unsigned o = 0;
        for (int k = 0; k < 32; k++) o |= d_z3[k * 512 + j];
        d_zf3[j] = (o != 0);
    }
}

// ---------------- layer 1: fp32 GEMM (x[32768,64] x sign(w1)^T[64,2048]) --------
// block: 256 threads, 8 rows x 1024 cols per block (4 col-groups of 256).
__global__ __launch_bounds__(256) void l1_kernel(
    const float* __restrict__ x, const float* __restrict__ b1,
    const float* __restrict__ g1, const float* __restrict__ be1,
    const float* __restrict__ m1, const float* __restrict__ v1)
{
    __shared__ __align__(16) float xs[8][64];
    int tid  = threadIdx.x;
    int row0 = blockIdx.y * 8;
    int jb   = blockIdx.x * 1024 + tid;

    for (int i = tid; i < 512; i += 256) xs[i >> 6][i & 63] = x[row0 * 64 + i];
    __syncthreads();

    float acc[4][8];
    #pragma unroll
    for (int g = 0; g < 4; g++)
        #pragma unroll
        for (int r = 0; r < 8; r++) acc[g][r] = 0.f;

    #pragma unroll 4
    for (int k4 = 0; k4 < 64; k4 += 4) {
        float4 wv[4];
        #pragma unroll
        for (int g = 0; g < 4; g++)
            wv[g] = *(const float4*)&d_s1k[((k4 >> 2) * 2048 + jb + g * 256) * 4];
        #pragma unroll
        for (int r = 0; r < 8; r++) {
            float4 xv = *(const float4*)&xs[r][k4];
            #pragma unroll
            for (int g = 0; g < 4; g++) {
                acc[g][r] = fmaf(xv.x, wv[g].x, acc[g][r]);
                acc[g][r] = fmaf(xv.y, wv[g].y, acc[g][r]);
                acc[g][r] = fmaf(xv.z, wv[g].z, acc[g][r]);
                acc[g][r] = fmaf(xv.w, wv[g].w, acc[g][r]);
            }
        }
    }

    #pragma unroll
    for (int g = 0; g < 4; g++) {
        int j = jb + g * 256;
        float sc  = g1[j] / sqrtf(v1[j] + EPSBN);
        float off = be1[j] - m1[j] * sc;
        float bb  = b1[j];
        #pragma unroll
        for (int r = 0; r < 8; r++) {
            float t = (acc[g][r] + bb) * sc + off;
            unsigned msk = __ballot_sync(0xffffffffu, t > 0.f);
            if ((tid & 31) == 0) d_h1[(row0 + r) * 64 + (j >> 5)] = msk;
        }
    }
}

// ---------------- layer 2: popcount GEMM (2048 -> 1024) ------------------------
// block: 256 threads (one output column each), 16 rows per block.
__global__ __launch_bounds__(256) void l2_kernel(
    const float* __restrict__ b2, const float* __restrict__ g2,
    const float* __restrict__ be2, const float* __restrict__ m2,
    const float* __restrict__ v2)
{
    __shared__ __align__(16) unsigned hs[16][64];
    __shared__ int Hrow[16];
    int tid  = threadIdx.x;
    int row0 = blockIdx.y * 16;
    int j    = blockIdx.x * 256 + tid;

    for (int i = tid; i < 1024; i += 256) hs[i >> 6][i & 63] = d_h1[row0 * 64 + i];
    __syncthreads();
    if (tid < 16) {
        int s = 0;
        for (int k = 0; k < 64; k++) s += __popc(hs[tid][k]);
        Hrow[tid] = s;
    }
    __syncthreads();

    unsigned a[16];
    #pragma unroll
    for (int r = 0; r < 16; r++) a[r] = 0u;

    #pragma unroll 4
    for (int k4 = 0; k4 < 64; k4 += 4) {
        uint4 p = *(const uint4*)&d_p2v[((k4 >> 2) * 1024 + j) * 4];
        #pragma unroll
        for (int r = 0; r < 16; r++) {
            uint4 h = *(const uint4*)&hs[r][k4];
            a[r] += __popc(h.x & p.x) + __popc(h.y & p.y) +
                    __popc(h.z & p.z) + __popc(h.w & p.w);
        }
    }

    float sc  = g2[j] / sqrtf(v2[j] + EPSBN);
    float off = be2[j] - m2[j] * sc;
    float bb  = b2[j];
    bool  hz  = d_zf2[j] != 0;
    #pragma unroll
    for (int r = 0; r < 16; r++) {
        int v = 2 * (int)a[r] - Hrow[r];
        if (hz) {
            for (int k = 0; k < 64; k++) v += __popc(hs[r][k] & d_z2[k * 1024 + j]);
        }
        float t = ((float)v + bb) * sc + off;
        unsigned msk = __ballot_sync(0xffffffffu, t > 0.f);
        if ((tid & 31) == 0) d_h2[(row0 + r) * 32 + (j >> 5)] = msk;
    }
}

// ---------------- layer 3: popcount GEMM (1024 -> 512) -------------------------
__global__ __launch_bounds__(256) void l3_kernel(
    const float* __restrict__ b3, const float* __restrict__ g3,
    const float* __restrict__ be3, const float* __restrict__ m3,
    const float* __restrict__ v3)
{
    __shared__ __align__(16) unsigned hs[16][32];
    __shared__ int Hrow[16];
    int tid  = threadIdx.x;
    int row0 = blockIdx.y * 16;
    int j    = blockIdx.x * 256 + tid;

    for (int i = tid; i < 512; i += 256) hs[i >> 5][i & 31] = d_h2[row0 * 32 + i];
    __syncthreads();
    if (tid < 16) {
        int s = 0;
        for (int k = 0; k < 32; k++) s += __popc(hs[tid][k]);
        Hrow[tid] = s;
    }
    __syncthreads();

    unsigned a[16];
    #pragma unroll
    for (int r = 0; r < 16; r++) a[r] = 0u;

    #pragma unroll 4
    for (int k4 = 0; k4 < 32; k4 += 4) {
        uint4 p = *(const uint4*)&d_p3v[((k4 >> 2) * 512 + j) * 4];
        #pragma unroll
        for (int r = 0; r < 16; r++) {
            uint4 h = *(const uint4*)&hs[r][k4];
            a[r] += __popc(h.x & p.x) + __popc(h.y & p.y) +
                    __popc(h.z & p.z) + __popc(h.w & p.w);
        }
    }

    float sc  = g3[j] / sqrtf(v3[j] + EPSBN);
    float off = be3[j] - m3[j] * sc;
    float bb  = b3[j];
    bool  hz  = d_zf3[j] != 0;
    #pragma unroll
    for (int r = 0; r < 16; r++) {
        int v = 2 * (int)a[r] - Hrow[r];
        if (hz) {
            for (int k = 0; k < 32; k++) v += __popc(hs[r][k] & d_z3[k * 512 + j]);
        }
        float t = ((float)v + bb) * sc + off;
        unsigned msk = __ballot_sync(0xffffffffu, t > 0.f);
        if ((tid & 31) == 0) d_h3[(row0 + r) * 16 + (j >> 5)] = msk;
    }
}

// ---------------- layer 4 + layer 5 + sigmoid (fused) --------------------------
__global__ __launch_bounds__(128) void out_kernel(
    const float* __restrict__ b4, const float* __restrict__ g4,
    const float* __restrict__ be4, const float* __restrict__ m4,
    const float* __restrict__ v4, const float* __restrict__ w5,
    const float* __restrict__ b5, float* __restrict__ out)
{
    __shared__ unsigned p4s[64 * 16], n4s[64 * 16];
    __shared__ float sc4[64], off4[64], bb4[64], w5s[64];
    int tid = threadIdx.x;
    for (int i = tid; i < 1024; i += 128) { p4s[i] = d_p4[i]; n4s[i] = d_n4[i]; }
    if (tid < 64) {
        float sc = g4[tid] / sqrtf(v4[tid] + EPSBN);
        sc4[tid] = sc;
        off4[tid] = be4[tid] - m4[tid] * sc;
        bb4[tid]  = b4[tid];
        w5s[tid]  = w5[tid];
    }
    __syncthreads();

    int row = blockIdx.x * 128 + tid;
    unsigned h[16];
    #pragma unroll
    for (int q = 0; q < 4; q++) {
        uint4 t = *(const uint4*)&d_h3[row * 16 + q * 4];
        h[q * 4] = t.x; h[q * 4 + 1] = t.y; h[q * 4 + 2] = t.z; h[q * 4 + 3] = t.w;
    }

    float z = b5[0];
    #pragma unroll 4
    for (int j = 0; j < 64; j++) {
        int a = 0, bn = 0;
        #pragma unroll
        for (int k = 0; k < 16; k++) {
            a  += __popc(h[k] & p4s[j * 16 + k]);
            bn += __popc(h[k] & n4s[j * 16 + k]);
        }
        float t = ((float)(a - bn) + bb4[j]) * sc4[j] + off4[j];
        if (t > 0.f) z += w5s[j];
    }
    out[row] = 1.f / (1.f + expf(-z));
}

// ---------------- launch ---------------------------------------------------------
extern "C" void kernel_launch(void* const* d_in, const int* in_sizes, int n_in,
                              void* d_out, int out_size) {
    const float* x   = (const float*)d_in[0];
    const float* w1  = (const float*)d_in[1];
    const float* b1  = (const float*)d_in[2];
    const float* w2  = (const float*)d_in[3];
    const float* b2  = (const float*)d_in[4];
    const float* w3  = (const float*)d_in[5];
    const float* b3  = (const float*)d_in[6];
    const float* w4  = (const float*)d_in[7];
    const float* b4  = (const float*)d_in[8];
    const float* w5  = (const float*)d_in[9];
    const float* b5  = (const float*)d_in[10];
    const float* g1  = (const float*)d_in[11];
    const float* be1 = (const float*)d_in[12];
    const float* m1  = (const float*)d_in[13];
    const float* v1  = (const float*)d_in[14];
    const float* g2  = (const float*)d_in[15];
    const float* be2 = (const float*)d_in[16];
    const float* m2  = (const float*)d_in[17];
    const float* v2  = (const float*)d_in[18];
    const float* g3  = (const float*)d_in[19];
    const float* be3 = (const float*)d_in[20];
    const float* m3  = (const float*)d_in[21];
    const float* v3  = (const float*)d_in[22];
    const float* g4  = (const float*)d_in[23];
    const float* be4 = (const float*)d_in[24];
    const float* m4  = (const float*)d_in[25];
    const float* v4  = (const float*)d_in[26];
    float* out = (float*)d_out;

    pack_s1<<<512, 256>>>(w1);
    pack_w<<<324, 256>>>(w2, w3, w4);
    zflags_kernel<<<6, 256>>>();
    l1_kernel<<<dim3(2, 4096), 256>>>(x, b1, g1, be1, m1, v1);
    l2_kernel<<<dim3(4, 2048), 256>>>(b2, g2, be2, m2, v2);
    l3_kernel<<<dim3(2, 2048), 256>>>(b3, g3, be3, m3, v3);
    out_kernel<<<256, 128>>>(b4, g4, be4, m4, v4, w5, b5, out);
}